// round 15
// baseline (speedup 1.0000x reference)
#include <cuda_runtime.h>
#include <cuda_fp16.h>
#include <cstdint>
#include <cstddef>

// ===========================================================================
// AttnBlock, fp16 mma.sync, token-major intermediates, cp.async pipeline,
// warp tile 64x64 (LDSM-per-MMA ratio 0.25), fp16 scores + in-place softmax.
// b=32, c=512, n=1024, groups=16
// ===========================================================================

#define BATCH 32
#define CCH   512
#define NTOK  1024
#define NGRP  16
#define CPG   (CCH / NGRP)
#define GSIZE (CPG * NTOK)

__device__ __half sc_hnT [(size_t)BATCH * NTOK * CCH];
__device__ __half sc_qkv [(size_t)BATCH * NTOK * 3 * CCH];
__device__ __half sc_at  [(size_t)BATCH * NTOK * NTOK];   // scores -> attn (in place)
__device__ __half sc_oT  [(size_t)BATCH * NTOK * CCH];
__device__ __half sc_wcat[(size_t)3 * CCH * CCH];
__device__ __half sc_wp  [(size_t)CCH * CCH];
__device__ float  sc_bcat[3 * CCH];

// Row-major operand: [row 0..127][kw 0..31], pitch 36 words (18432 B).
// Trans-B operand:   [k 0..63][n-half 0..63], pitch 68 words (17408 B).
// Both: 8 consecutive rows start at {0,4,...,28} mod 32 -> ldmatrix
// 16B-granule reads tile all 32 banks, conflict-free.
#define PITCHW  36
#define PITCHBT 68
#define OPW     (128 * PITCHW)             // words per operand slot (4608)
#define GEMM_SMEM_BYTES (4 * OPW * 4)      // A0 B0 A1 B1 = 73728 B
#define GTHREADS 128                        // 4 warps per GEMM CTA

__device__ __forceinline__ void cpa16(uint32_t saddr, const void* g) {
    asm volatile("cp.async.cg.shared.global [%0], [%1], 16;"
                 :: "r"(saddr), "l"(g));
}
#define CPA_COMMIT() asm volatile("cp.async.commit_group;" ::: "memory")
#define CPA_WAIT1()  asm volatile("cp.async.wait_group 1;" ::: "memory")
#define CPA_WAIT0()  asm volatile("cp.async.wait_group 0;" ::: "memory")

// row-major tile: 128 rows x 64 halves (128 threads)
__device__ __forceinline__ void cpa_tile(uint32_t sbase_bytes,
                                         const __half* __restrict__ src,
                                         int ld, int row0, int k0, int t) {
    #pragma unroll
    for (int j = 0; j < 8; j++) {
        const int idx = t + GTHREADS * j;
        const int r = idx >> 3, c8 = idx & 7;
        const void* g = src + (size_t)(row0 + r) * ld + k0 + c8 * 8;
        cpa16(sbase_bytes + (uint32_t)(r * PITCHW + c8 * 4) * 4u, g);
    }
}

// trans tile: 64 k-rows x 128 n-halves, native [k][n] layout (128 threads)
__device__ __forceinline__ void cpa_tile_bt(uint32_t sbase_bytes,
                                            const __half* __restrict__ src,
                                            int ld, int n0, int k0, int t) {
    #pragma unroll
    for (int j = 0; j < 8; j++) {
        const int idx = t + GTHREADS * j;
        const int r = idx >> 4, c16 = idx & 15;
        const void* g = src + (size_t)(k0 + r) * ld + n0 + c16 * 8;
        cpa16(sbase_bytes + (uint32_t)(r * PITCHBT + c16 * 4) * 4u, g);
    }
}

__device__ __forceinline__ void mma16816(float d[4], const uint32_t a[4],
                                         const uint32_t b[2]) {
    asm volatile(
        "mma.sync.aligned.m16n8k16.row.col.f32.f16.f16.f32 "
        "{%0,%1,%2,%3}, {%4,%5,%6,%7}, {%8,%9}, {%0,%1,%2,%3};"
        : "+f"(d[0]), "+f"(d[1]), "+f"(d[2]), "+f"(d[3])
        : "r"(a[0]), "r"(a[1]), "r"(a[2]), "r"(a[3]), "r"(b[0]), "r"(b[1]));
}
#define LDMX4(r0, r1, r2, r3, addr) \
    asm volatile("ldmatrix.sync.aligned.m8n8.x4.shared.b16 {%0,%1,%2,%3}, [%4];" \
                 : "=r"(r0), "=r"(r1), "=r"(r2), "=r"(r3) : "r"(addr))
#define LDMX4T(r0, r1, r2, r3, addr) \
    asm volatile("ldmatrix.sync.aligned.m8n8.x4.trans.shared.b16 {%0,%1,%2,%3}, [%4];" \
                 : "=r"(r0), "=r"(r1), "=r"(r2), "=r"(r3) : "r"(addr))

// Load one ks-step's fragments. Warp tile 64x64:
//   A: 4x ldmatrix.x4 (mf 0..3);  B: 4x ldmatrix(.trans).x4 (nf pairs 0..3)
template<int BT>
__device__ __forceinline__ void load_frags(uint32_t aBuf, uint32_t bBuf,
                                           uint32_t laneA, uint32_t laneB,
                                           int ks, uint32_t af[4][4],
                                           uint32_t bf[8][2]) {
    #pragma unroll
    for (int mf = 0; mf < 4; mf++)
        LDMX4(af[mf][0], af[mf][1], af[mf][2], af[mf][3],
              aBuf + laneA + (uint32_t)(mf * 16 * PITCHW * 4 + ks * 32));
    #pragma unroll
    for (int p = 0; p < 4; p++) {
        if (BT == 0) {
            LDMX4(bf[2 * p][0], bf[2 * p][1], bf[2 * p + 1][0], bf[2 * p + 1][1],
                  bBuf + laneB + (uint32_t)(p * 16 * PITCHW * 4 + ks * 32));
        } else {
            LDMX4T(bf[2 * p][0], bf[2 * p][1], bf[2 * p + 1][0], bf[2 * p + 1][1],
                   bBuf + laneB + (uint32_t)(ks * 16 * PITCHBT * 4 + p * 32));
        }
    }
}

// ---------------------------------------------------------------------------
// GEMM: C[m][n] = scale * sum_k A[m][k]*B'[n][k] (+bias) (+resid)
// A row-major (cp.async). BT=0: B row-major [n][k]; BT=1: B native [k][n]
// (cp.async + ldmatrix.trans). BIASMODE 0/1(row)/2(col). HOUT fp16/fp32.
// 128x128x64 CTA tile, 4 warps (2Mx2N, warp tile 64x64), 2-stage cp.async,
// register double-buffered fragments.
// ---------------------------------------------------------------------------
template<int BT, int BIASMODE, bool RESID, bool HOUT>
__global__ void __launch_bounds__(GTHREADS, 2) hgemm(
    const __half* __restrict__ A, const __half* __restrict__ B,
    const float* __restrict__ bias, const float* __restrict__ resid,
    void* __restrict__ Cv, int N, int K, int ldA, int ldB,
    size_t sA, size_t sB, size_t sC, size_t sR, float scale)
{
    extern __shared__ __align__(16) uint32_t smbuf[];

    const int z = blockIdx.z;
    A += (size_t)z * sA;
    B += (size_t)z * sB;
    const float* R = RESID ? (resid + (size_t)z * sR) : nullptr;

    const int n0 = blockIdx.x * 128, m0 = blockIdx.y * 128;
    const int t = threadIdx.x;
    const int wid = t >> 5, lane = t & 31;
    const int wm = wid & 1, wn = wid >> 1;      // 2(M) x 2(N) warps
    const int grp = lane >> 2, tig = lane & 3;

    const uint32_t smBase = (uint32_t)__cvta_generic_to_shared(smbuf);

    float acc[4][8][4] = {};

    // prologue: chunk 0
    cpa_tile(smBase, A, ldA, m0, 0, t);
    if (BT == 0) cpa_tile(smBase + OPW * 4, B, ldB, n0, 0, t);
    else         cpa_tile_bt(smBase + OPW * 4, B, ldB, n0, 0, t);
    CPA_COMMIT();

    const uint32_t laneA =
        ((uint32_t)(wm * 64 + (lane & 7) + 8 * ((lane >> 3) & 1)) * PITCHW
         + 4u * ((lane >> 4) & 1)) * 4u;
    const uint32_t laneB = (BT == 0)
        ? ((uint32_t)(wn * 64 + (lane & 7) + 8 * ((lane >> 4) & 1)) * PITCHW
           + 4u * ((lane >> 3) & 1)) * 4u
        : (uint32_t)((lane & 7) + 8 * ((lane >> 3) & 1)) * (PITCHBT * 4)
          + (uint32_t)(wn * 64 + 8 * ((lane >> 4) & 1)) * 2u;

    const int NK = K >> 6;
    for (int kc = 0; kc < NK; kc++) {
        const bool more = (kc + 1 < NK);
        const uint32_t cur = (kc & 1) ? (uint32_t)(2 * OPW * 4) : 0u;
        const uint32_t nxt = (kc & 1) ? 0u : (uint32_t)(2 * OPW * 4);
        if (more) {
            cpa_tile(smBase + nxt, A, ldA, m0, (kc + 1) * 64, t);
            if (BT == 0) cpa_tile(smBase + nxt + OPW * 4, B, ldB, n0, (kc + 1) * 64, t);
            else         cpa_tile_bt(smBase + nxt + OPW * 4, B, ldB, n0, (kc + 1) * 64, t);
            CPA_COMMIT();
        }
        if (more) CPA_WAIT1(); else CPA_WAIT0();
        __syncthreads();

        const uint32_t aBuf = smBase + cur;
        const uint32_t bBuf = aBuf + (uint32_t)(OPW * 4);

        uint32_t af[2][4][4], bf[2][8][2];
        load_frags<BT>(aBuf, bBuf, laneA, laneB, 0, af[0], bf[0]);
        #pragma unroll
        for (int ks = 0; ks < 4; ks++) {
            const int cb = ks & 1;
            if (ks < 3)
                load_frags<BT>(aBuf, bBuf, laneA, laneB, ks + 1, af[cb ^ 1], bf[cb ^ 1]);
            #pragma unroll
            for (int mf = 0; mf < 4; mf++)
                #pragma unroll
                for (int nf = 0; nf < 8; nf++)
                    mma16816(acc[mf][nf], af[cb][mf], bf[cb][nf]);
        }
        __syncthreads();
    }

    // ---- epilogue ----
    #pragma unroll
    for (int mf = 0; mf < 4; mf++) {
        const int r0 = m0 + wm * 64 + mf * 16 + grp;
        const float ba0 = (BIASMODE == 1) ? bias[r0] : 0.f;
        const float ba1 = (BIASMODE == 1) ? bias[r0 + 8] : 0.f;
        #pragma unroll
        for (int nf = 0; nf < 8; nf++) {
            const int cc = n0 + wn * 64 + nf * 8 + 2 * tig;
            float cb0 = 0.f, cb1 = 0.f;
            if (BIASMODE == 2) {
                const float2 cb = *reinterpret_cast<const float2*>(&bias[cc]);
                cb0 = cb.x; cb1 = cb.y;
            }
            float2 v0, v1;
            v0.x = acc[mf][nf][0] * scale + ba0 + cb0;
            v0.y = acc[mf][nf][1] * scale + ba0 + cb1;
            v1.x = acc[mf][nf][2] * scale + ba1 + cb0;
            v1.y = acc[mf][nf][3] * scale + ba1 + cb1;
            if (RESID) {
                const float2 q0 = *reinterpret_cast<const float2*>(&R[(size_t)r0 * N + cc]);
                const float2 q1 = *reinterpret_cast<const float2*>(&R[(size_t)(r0 + 8) * N + cc]);
                v0.x += q0.x; v0.y += q0.y;
                v1.x += q1.x; v1.y += q1.y;
            }
            if (HOUT) {
                __half* C = (__half*)Cv + (size_t)z * sC;
                *reinterpret_cast<__half2*>(&C[(size_t)r0 * N + cc]) =
                    __floats2half2_rn(v0.x, v0.y);
                *reinterpret_cast<__half2*>(&C[(size_t)(r0 + 8) * N + cc]) =
                    __floats2half2_rn(v1.x, v1.y);
            } else {
                float* C = (float*)Cv + (size_t)z * sC;
                *reinterpret_cast<float2*>(&C[(size_t)r0 * N + cc]) = v0;
                *reinterpret_cast<float2*>(&C[(size_t)(r0 + 8) * N + cc]) = v1;
            }
        }
    }
}

// ---------------------------------------------------------------------------
// Weight + bias conversion, one launch: zz 0..2 -> wcat, 3 -> wp, 4 -> bcat
// ---------------------------------------------------------------------------
__global__ void __launch_bounds__(256) cvt_wb_kernel(
    const float* __restrict__ w0, const float* __restrict__ w1,
    const float* __restrict__ w2, const float* __restrict__ w3,
    const float* __restrict__ b0, const float* __restrict__ b1,
    const float* __restrict__ b2,
    __half* __restrict__ wcat, __half* __restrict__ wp,
    float* __restrict__ bcat)
{
    const int zz = blockIdx.y;
    const int i = blockIdx.x * 256 + threadIdx.x;
    if (zz == 4) {
        if (i < 3 * CCH)
            bcat[i] = (i < 512) ? b0[i] : (i < 1024) ? b1[i - 512] : b2[i - 1024];
        return;
    }
    const float* src = (zz == 0) ? w0 : (zz == 1) ? w1 : (zz == 2) ? w2 : w3;
    __half* dst = (zz == 3) ? wp : (wcat + (size_t)zz * CCH * CCH);
    const float4 v = reinterpret_cast<const float4*>(src)[i];
    __half2* d = reinterpret_cast<__half2*>(dst) + i * 2;
    d[0] = __floats2half2_rn(v.x, v.y);
    d[1] = __floats2half2_rn(v.z, v.w);
}

// ---------------------------------------------------------------------------
// GroupNorm -> token-major fp16
// ---------------------------------------------------------------------------
__global__ void __launch_bounds__(256) groupnorm_t_kernel(
    const float* __restrict__ x, const float* __restrict__ gamma,
    const float* __restrict__ beta, __half* __restrict__ hnT)
{
    const int g = blockIdx.x, b = blockIdx.y;
    const int c0 = g * CPG;
    const size_t xbase = ((size_t)b * CCH + c0) * NTOK;
    const int tid = threadIdx.x;

    const float4* xp = reinterpret_cast<const float4*>(x + xbase);
    float s = 0.f, ss = 0.f;
    for (int i = tid; i < GSIZE / 4; i += 256) {
        const float4 v = xp[i];
        s  += v.x + v.y + v.z + v.w;
        ss += v.x * v.x + v.y * v.y + v.z * v.z + v.w * v.w;
    }
    __shared__ float rs[256], rss[256];
    rs[tid] = s; rss[tid] = ss;
    __syncthreads();
    for (int w = 128; w > 0; w >>= 1) {
        if (tid < w) { rs[tid] += rs[tid + w]; rss[tid] += rss[tid + w]; }
        __syncthreads();
    }
    const float mean = rs[0] * (1.f / GSIZE);
    const float var  = rss[0] * (1.f / GSIZE) - mean * mean;
    const float rstd = rsqrtf(var + 1e-6f);

    __shared__ float gsc[CPG], gof[CPG];
    if (tid < CPG) {
        const float ga = gamma[c0 + tid] * rstd;
        gsc[tid] = ga;
        gof[tid] = beta[c0 + tid] - mean * ga;
    }
    __syncthreads();

    __shared__ __half smh[32 * 264];
    for (int tt = 0; tt < 4; tt++) {
        const int tok0 = tt * 256;
        #pragma unroll 4
        for (int j = 0; j < 32; j++) {
            const float val = x[xbase + (size_t)j * NTOK + tok0 + tid];
            smh[j * 264 + tid] = __float2half(val * gsc[j] + gof[j]);
        }
        __syncthreads();
        const size_t obase = ((size_t)b * NTOK + tok0 + tid) * CCH + c0;
        __half2 wb[16];
        #pragma unroll
        for (int j2 = 0; j2 < 16; j2++) {
            const __half lo = smh[(2 * j2) * 264 + tid];
            const __half hi = smh[(2 * j2 + 1) * 264 + tid];
            wb[j2] = __halves2half2(lo, hi);
        }
        #pragma unroll
        for (int qd = 0; qd < 4; qd++) {
            *reinterpret_cast<uint4*>(&hnT[obase + qd * 8]) =
                *reinterpret_cast<const uint4*>(&wb[qd * 4]);
        }
        __syncthreads();
    }
}

// ---------------------------------------------------------------------------
// Warp-per-row softmax, fp16 in/out, IN PLACE. Pure shuffle reductions.
// (per-row max == reference's global shift, by softmax shift invariance)
// ---------------------------------------------------------------------------
__global__ void __launch_bounds__(256) softmax_kernel(__half* __restrict__ at)
{
    const int wid = threadIdx.x >> 5, lane = threadIdx.x & 31;
    const size_t row = (size_t)blockIdx.y * NTOK + blockIdx.x * 8 + wid;
    uint4* p = reinterpret_cast<uint4*>(at + row * NTOK);

    uint4 raw[4];
    float v[4][8];
    float m = -3.4e38f;
    #pragma unroll
    for (int i = 0; i < 4; i++) {
        raw[i] = p[lane + 32 * i];
        const uint32_t* w = reinterpret_cast<const uint32_t*>(&raw[i]);
        #pragma unroll
        for (int j = 0; j < 4; j++) {
            const float2 f = __half22float2(*reinterpret_cast<const __half2*>(&w[j]));
            v[i][2 * j] = f.x; v[i][2 * j + 1] = f.y;
            m = fmaxf(m, fmaxf(f.x, f.y));
        }
    }
    #pragma unroll
    for (int off = 16; off > 0; off >>= 1)
        m = fmaxf(m, __shfl_xor_sync(0xFFFFFFFFu, m, off));

    float sum = 0.f;
    #pragma unroll
    for (int i = 0; i < 4; i++)
        #pragma unroll
        for (int j = 0; j < 8; j++) {
            v[i][j] = __expf(v[i][j] - m);
            sum += v[i][j];
        }
    #pragma unroll
    for (int off = 16; off > 0; off >>= 1)
        sum += __shfl_xor_sync(0xFFFFFFFFu, sum, off);
    const float inv = 1.f / sum;

    #pragma unroll
    for (int i = 0; i < 4; i++) {
        uint4 outw;
        uint32_t* w = reinterpret_cast<uint32_t*>(&outw);
        #pragma unroll
        for (int j = 0; j < 4; j++) {
            const __half2 h = __floats2half2_rn(v[i][2 * j] * inv, v[i][2 * j + 1] * inv);
            w[j] = *reinterpret_cast<const uint32_t*>(&h);
        }
        p[lane + 32 * i] = outw;
    }
}

// ---------------------------------------------------------------------------
extern "C" void kernel_launch(void* const* d_in, const int* in_sizes, int n_in,
                              void* d_out, int out_size)
{
    (void)in_sizes; (void)n_in; (void)out_size;
    const float* x     = (const float*)d_in[0];
    const float* gamma = (const float*)d_in[1];
    const float* beta  = (const float*)d_in[2];
    const float* wq    = (const float*)d_in[3];
    const float* bq    = (const float*)d_in[4];
    const float* wk    = (const float*)d_in[5];
    const float* bk    = (const float*)d_in[6];
    const float* wv    = (const float*)d_in[7];
    const float* bv    = (const float*)d_in[8];
    const float* wp    = (const float*)d_in[9];
    const float* bp    = (const float*)d_in[10];
    float* out = (float*)d_out;

    void *p0, *p1, *p3, *p4, *p5, *p6, *p7;
    cudaGetSymbolAddress(&p0, sc_hnT);
    cudaGetSymbolAddress(&p1, sc_qkv);
    cudaGetSymbolAddress(&p3, sc_at);
    cudaGetSymbolAddress(&p4, sc_oT);
    cudaGetSymbolAddress(&p5, sc_wcat);
    cudaGetSymbolAddress(&p6, sc_wp);
    cudaGetSymbolAddress(&p7, sc_bcat);
    __half* hnT  = (__half*)p0;
    __half* qkv  = (__half*)p1;
    __half* at   = (__half*)p3;
    __half* oT   = (__half*)p4;
    __half* wcat = (__half*)p5;
    __half* whp  = (__half*)p6;
    float*  bcat = (float*)p7;

    const size_t sHN  = (size_t)NTOK * CCH;
    const size_t sQKV = (size_t)NTOK * 3 * CCH;
    const size_t sS   = (size_t)NTOK * NTOK;

    cudaFuncSetAttribute(hgemm<0, 2, false, true>,
        cudaFuncAttributeMaxDynamicSharedMemorySize, GEMM_SMEM_BYTES);
    cudaFuncSetAttribute(hgemm<0, 0, false, true>,
        cudaFuncAttributeMaxDynamicSharedMemorySize, GEMM_SMEM_BYTES);
    cudaFuncSetAttribute(hgemm<1, 0, false, true>,
        cudaFuncAttributeMaxDynamicSharedMemorySize, GEMM_SMEM_BYTES);
    cudaFuncSetAttribute(hgemm<0, 1, true, false>,
        cudaFuncAttributeMaxDynamicSharedMemorySize, GEMM_SMEM_BYTES);

    cvt_wb_kernel<<<dim3(256, 5), 256>>>(wq, wk, wv, wp, bq, bk, bv,
                                         wcat, whp, bcat);
    groupnorm_t_kernel<<<dim3(NGRP, BATCH), 256>>>(x, gamma, beta, hnT);

    // 1) fused QKV: qkv[token][oc'] = hnT[token][c] . wcat[oc'][c] + bcat[oc']
    hgemm<0, 2, false, true><<<dim3(12, 8, BATCH), GTHREADS, GEMM_SMEM_BYTES>>>(
        hnT, wcat, bcat, nullptr, qkv, 3 * CCH, CCH, CCH, CCH,
        sHN, 0, sQKV, 0, 1.f);

    // 2) scores (fp16 out) s[n][m] = scale * q[n][:] . k[m][:]
    hgemm<0, 0, false, true><<<dim3(8, 8, BATCH), GTHREADS, GEMM_SMEM_BYTES>>>(
        qkv, qkv + CCH, nullptr, nullptr, at, NTOK, CCH, 3 * CCH, 3 * CCH,
        sQKV, sQKV, sS, 0, 0.04419417382415922f);

    // 3) softmax, in place on fp16 scores
    softmax_kernel<<<dim3(NTOK / 8, BATCH), 256>>>(at);

    // 4) oT[n][c] = sum_m at[n][m] * v[m][c]
    //    (B = v native [k][n] layout -> cp.async + ldmatrix.trans)
    hgemm<1, 0, false, true><<<dim3(4, 8, BATCH), GTHREADS, GEMM_SMEM_BYTES>>>(
        at, qkv + 2 * CCH, nullptr, nullptr, oT, CCH, NTOK, NTOK, 3 * CCH,
        sS, sQKV, sHN, 0, 1.f);

    // 5) out[oc][n] = x + wp[oc][:] . oT[n][:] + bp[oc]
    hgemm<0, 1, true, false><<<dim3(8, 4, BATCH), GTHREADS, GEMM_SMEM_BYTES>>>(
        whp, oT, bp, x, out, NTOK, CCH, CCH, CCH,
        0, sHN, sHN, sHN, 1.f);
}

// round 16
// speedup vs baseline: 1.0133x; 1.0133x over previous
#include <cuda_runtime.h>
#include <cuda_fp16.h>
#include <cstdint>
#include <cstddef>

// ===========================================================================
// AttnBlock, fp16 mma.sync, token-major intermediates, cp.async pipeline.
// GEMMs at measured mma.sync floor (16 cyc/mma/SMSP): QKV/attnV/proj use
// 256-thr 64x32-warp variant; scores uses 128-thr 64x64 variant (measured
// faster). Merged prep launch + conflict-free GN transpose.
// b=32, c=512, n=1024, groups=16
// ===========================================================================

#define BATCH 32
#define CCH   512
#define NTOK  1024
#define NGRP  16
#define CPG   (CCH / NGRP)
#define GSIZE (CPG * NTOK)

__device__ __half sc_hnT [(size_t)BATCH * NTOK * CCH];
__device__ __half sc_qkv [(size_t)BATCH * NTOK * 3 * CCH];
__device__ __half sc_at  [(size_t)BATCH * NTOK * NTOK];   // scores -> attn (in place)
__device__ __half sc_oT  [(size_t)BATCH * NTOK * CCH];
__device__ __half sc_wcat[(size_t)3 * CCH * CCH];
__device__ __half sc_wp  [(size_t)CCH * CCH];
__device__ float  sc_bcat[3 * CCH];

#define PITCHW  36
#define PITCHBT 68
#define OPW     (128 * PITCHW)             // words per operand slot (4608)
#define GEMM_SMEM_BYTES (4 * OPW * 4)      // A0 B0 A1 B1 = 73728 B

__device__ __forceinline__ void cpa16(uint32_t saddr, const void* g) {
    asm volatile("cp.async.cg.shared.global [%0], [%1], 16;"
                 :: "r"(saddr), "l"(g));
}
#define CPA_COMMIT() asm volatile("cp.async.commit_group;" ::: "memory")
#define CPA_WAIT1()  asm volatile("cp.async.wait_group 1;" ::: "memory")
#define CPA_WAIT0()  asm volatile("cp.async.wait_group 0;" ::: "memory")

// row-major tile: 128 rows x 64 halves; NT = thread count
template<int NT>
__device__ __forceinline__ void cpa_tile(uint32_t sbase_bytes,
                                         const __half* __restrict__ src,
                                         int ld, int row0, int k0, int t) {
    #pragma unroll
    for (int j = 0; j < 1024 / NT; j++) {
        const int idx = t + NT * j;
        const int r = idx >> 3, c8 = idx & 7;
        const void* g = src + (size_t)(row0 + r) * ld + k0 + c8 * 8;
        cpa16(sbase_bytes + (uint32_t)(r * PITCHW + c8 * 4) * 4u, g);
    }
}

// trans tile: 64 k-rows x 128 n-halves, native [k][n] layout
template<int NT>
__device__ __forceinline__ void cpa_tile_bt(uint32_t sbase_bytes,
                                            const __half* __restrict__ src,
                                            int ld, int n0, int k0, int t) {
    #pragma unroll
    for (int j = 0; j < 1024 / NT; j++) {
        const int idx = t + NT * j;
        const int r = idx >> 4, c16 = idx & 15;
        const void* g = src + (size_t)(k0 + r) * ld + n0 + c16 * 8;
        cpa16(sbase_bytes + (uint32_t)(r * PITCHBT + c16 * 4) * 4u, g);
    }
}

__device__ __forceinline__ void mma16816(float d[4], const uint32_t a[4],
                                         const uint32_t b[2]) {
    asm volatile(
        "mma.sync.aligned.m16n8k16.row.col.f32.f16.f16.f32 "
        "{%0,%1,%2,%3}, {%4,%5,%6,%7}, {%8,%9}, {%0,%1,%2,%3};"
        : "+f"(d[0]), "+f"(d[1]), "+f"(d[2]), "+f"(d[3])
        : "r"(a[0]), "r"(a[1]), "r"(a[2]), "r"(a[3]), "r"(b[0]), "r"(b[1]));
}
#define LDMX4(r0, r1, r2, r3, addr) \
    asm volatile("ldmatrix.sync.aligned.m8n8.x4.shared.b16 {%0,%1,%2,%3}, [%4];" \
                 : "=r"(r0), "=r"(r1), "=r"(r2), "=r"(r3) : "r"(addr))
#define LDMX4T(r0, r1, r2, r3, addr) \
    asm volatile("ldmatrix.sync.aligned.m8n8.x4.trans.shared.b16 {%0,%1,%2,%3}, [%4];" \
                 : "=r"(r0), "=r"(r1), "=r"(r2), "=r"(r3) : "r"(addr))

// ---------------------------------------------------------------------------
// 256-thread GEMM (8 warps, 2Mx4N, warp tile 64x32) — R14-proven variant.
// ---------------------------------------------------------------------------
template<int BT>
__device__ __forceinline__ void load_frags256(uint32_t aBuf, uint32_t bBuf,
                                              uint32_t laneA, uint32_t laneB,
                                              int ks, uint32_t af[4][4],
                                              uint32_t bf[4][2]) {
    #pragma unroll
    for (int mf = 0; mf < 4; mf++)
        LDMX4(af[mf][0], af[mf][1], af[mf][2], af[mf][3],
              aBuf + laneA + (uint32_t)(mf * 16 * PITCHW * 4 + ks * 32));
    if (BT == 0) {
        LDMX4(bf[0][0], bf[0][1], bf[1][0], bf[1][1],
              bBuf + laneB + (uint32_t)(ks * 32));
        LDMX4(bf[2][0], bf[2][1], bf[3][0], bf[3][1],
              bBuf + laneB + (uint32_t)(16 * PITCHW * 4 + ks * 32));
    } else {
        LDMX4T(bf[0][0], bf[0][1], bf[1][0], bf[1][1],
               bBuf + laneB + (uint32_t)(ks * 16 * PITCHBT * 4));
        LDMX4T(bf[2][0], bf[2][1], bf[3][0], bf[3][1],
               bBuf + laneB + (uint32_t)(ks * 16 * PITCHBT * 4 + 32));
    }
}

template<int BT, int BIASMODE, bool RESID, bool HOUT>
__global__ void __launch_bounds__(256, 2) hgemm(
    const __half* __restrict__ A, const __half* __restrict__ B,
    const float* __restrict__ bias, const float* __restrict__ resid,
    void* __restrict__ Cv, int N, int K, int ldA, int ldB,
    size_t sA, size_t sB, size_t sC, size_t sR, float scale)
{
    extern __shared__ __align__(16) uint32_t smbuf[];

    const int z = blockIdx.z;
    A += (size_t)z * sA;
    B += (size_t)z * sB;
    const float* R = RESID ? (resid + (size_t)z * sR) : nullptr;

    const int n0 = blockIdx.x * 128, m0 = blockIdx.y * 128;
    const int t = threadIdx.x;
    const int wid = t >> 5, lane = t & 31;
    const int wm = wid & 1, wn = wid >> 1;
    const int grp = lane >> 2, tig = lane & 3;

    const uint32_t smBase = (uint32_t)__cvta_generic_to_shared(smbuf);

    float acc[4][4][4] = {};

    cpa_tile<256>(smBase, A, ldA, m0, 0, t);
    if (BT == 0) cpa_tile<256>(smBase + OPW * 4, B, ldB, n0, 0, t);
    else         cpa_tile_bt<256>(smBase + OPW * 4, B, ldB, n0, 0, t);
    CPA_COMMIT();

    const uint32_t laneA =
        ((uint32_t)(wm * 64 + (lane & 7) + 8 * ((lane >> 3) & 1)) * PITCHW
         + 4u * ((lane >> 4) & 1)) * 4u;
    const uint32_t laneB = (BT == 0)
        ? ((uint32_t)(wn * 32 + (lane & 7) + 8 * ((lane >> 4) & 1)) * PITCHW
           + 4u * ((lane >> 3) & 1)) * 4u
        : (uint32_t)((lane & 7) + 8 * ((lane >> 3) & 1)) * (PITCHBT * 4)
          + (uint32_t)(wn * 32 + 8 * ((lane >> 4) & 1)) * 2u;

    const int NK = K >> 6;
    for (int kc = 0; kc < NK; kc++) {
        const bool more = (kc + 1 < NK);
        const uint32_t cur = (kc & 1) ? (uint32_t)(2 * OPW * 4) : 0u;
        const uint32_t nxt = (kc & 1) ? 0u : (uint32_t)(2 * OPW * 4);
        if (more) {
            cpa_tile<256>(smBase + nxt, A, ldA, m0, (kc + 1) * 64, t);
            if (BT == 0) cpa_tile<256>(smBase + nxt + OPW * 4, B, ldB, n0, (kc + 1) * 64, t);
            else         cpa_tile_bt<256>(smBase + nxt + OPW * 4, B, ldB, n0, (kc + 1) * 64, t);
            CPA_COMMIT();
        }
        if (more) CPA_WAIT1(); else CPA_WAIT0();
        __syncthreads();

        const uint32_t aBuf = smBase + cur;
        const uint32_t bBuf = aBuf + (uint32_t)(OPW * 4);

        uint32_t af[2][4][4], bf[2][4][2];
        load_frags256<BT>(aBuf, bBuf, laneA, laneB, 0, af[0], bf[0]);
        #pragma unroll
        for (int ks = 0; ks < 4; ks++) {
            const int cb = ks & 1;
            if (ks < 3)
                load_frags256<BT>(aBuf, bBuf, laneA, laneB, ks + 1, af[cb ^ 1], bf[cb ^ 1]);
            #pragma unroll
            for (int mf = 0; mf < 4; mf++)
                #pragma unroll
                for (int nf = 0; nf < 4; nf++)
                    mma16816(acc[mf][nf], af[cb][mf], bf[cb][nf]);
        }
        __syncthreads();
    }

    #pragma unroll
    for (int mf = 0; mf < 4; mf++) {
        const int r0 = m0 + wm * 64 + mf * 16 + grp;
        const float ba0 = (BIASMODE == 1) ? bias[r0] : 0.f;
        const float ba1 = (BIASMODE == 1) ? bias[r0 + 8] : 0.f;
        #pragma unroll
        for (int nf = 0; nf < 4; nf++) {
            const int cc = n0 + wn * 32 + nf * 8 + 2 * tig;
            float cb0 = 0.f, cb1 = 0.f;
            if (BIASMODE == 2) {
                const float2 cb = *reinterpret_cast<const float2*>(&bias[cc]);
                cb0 = cb.x; cb1 = cb.y;
            }
            float2 v0, v1;
            v0.x = acc[mf][nf][0] * scale + ba0 + cb0;
            v0.y = acc[mf][nf][1] * scale + ba0 + cb1;
            v1.x = acc[mf][nf][2] * scale + ba1 + cb0;
            v1.y = acc[mf][nf][3] * scale + ba1 + cb1;
            if (RESID) {
                const float2 q0 = *reinterpret_cast<const float2*>(&R[(size_t)r0 * N + cc]);
                const float2 q1 = *reinterpret_cast<const float2*>(&R[(size_t)(r0 + 8) * N + cc]);
                v0.x += q0.x; v0.y += q0.y;
                v1.x += q1.x; v1.y += q1.y;
            }
            if (HOUT) {
                __half* C = (__half*)Cv + (size_t)z * sC;
                *reinterpret_cast<__half2*>(&C[(size_t)r0 * N + cc]) =
                    __floats2half2_rn(v0.x, v0.y);
                *reinterpret_cast<__half2*>(&C[(size_t)(r0 + 8) * N + cc]) =
                    __floats2half2_rn(v1.x, v1.y);
            } else {
                float* C = (float*)Cv + (size_t)z * sC;
                *reinterpret_cast<float2*>(&C[(size_t)r0 * N + cc]) = v0;
                *reinterpret_cast<float2*>(&C[(size_t)(r0 + 8) * N + cc]) = v1;
            }
        }
    }
}

// ---------------------------------------------------------------------------
// 128-thread GEMM (4 warps, 2Mx2N, warp tile 64x64) — R15 variant, scores only.
// ---------------------------------------------------------------------------
__device__ __forceinline__ void load_frags128(uint32_t aBuf, uint32_t bBuf,
                                              uint32_t laneA, uint32_t laneB,
                                              int ks, uint32_t af[4][4],
                                              uint32_t bf[8][2]) {
    #pragma unroll
    for (int mf = 0; mf < 4; mf++)
        LDMX4(af[mf][0], af[mf][1], af[mf][2], af[mf][3],
              aBuf + laneA + (uint32_t)(mf * 16 * PITCHW * 4 + ks * 32));
    #pragma unroll
    for (int p = 0; p < 4; p++)
        LDMX4(bf[2 * p][0], bf[2 * p][1], bf[2 * p + 1][0], bf[2 * p + 1][1],
              bBuf + laneB + (uint32_t)(p * 16 * PITCHW * 4 + ks * 32));
}

__global__ void __launch_bounds__(128, 2) hgemm_s(
    const __half* __restrict__ A, const __half* __restrict__ B,
    __half* __restrict__ C, int N, int K, int ldA, int ldB,
    size_t sA, size_t sB, size_t sC, float scale)
{
    extern __shared__ __align__(16) uint32_t smbuf[];

    const int z = blockIdx.z;
    A += (size_t)z * sA;
    B += (size_t)z * sB;
    C += (size_t)z * sC;

    const int n0 = blockIdx.x * 128, m0 = blockIdx.y * 128;
    const int t = threadIdx.x;
    const int wid = t >> 5, lane = t & 31;
    const int wm = wid & 1, wn = wid >> 1;
    const int grp = lane >> 2, tig = lane & 3;

    const uint32_t smBase = (uint32_t)__cvta_generic_to_shared(smbuf);

    float acc[4][8][4] = {};

    cpa_tile<128>(smBase, A, ldA, m0, 0, t);
    cpa_tile<128>(smBase + OPW * 4, B, ldB, n0, 0, t);
    CPA_COMMIT();

    const uint32_t laneA =
        ((uint32_t)(wm * 64 + (lane & 7) + 8 * ((lane >> 3) & 1)) * PITCHW
         + 4u * ((lane >> 4) & 1)) * 4u;
    const uint32_t laneB =
        ((uint32_t)(wn * 64 + (lane & 7) + 8 * ((lane >> 4) & 1)) * PITCHW
         + 4u * ((lane >> 3) & 1)) * 4u;

    const int NK = K >> 6;
    for (int kc = 0; kc < NK; kc++) {
        const bool more = (kc + 1 < NK);
        const uint32_t cur = (kc & 1) ? (uint32_t)(2 * OPW * 4) : 0u;
        const uint32_t nxt = (kc & 1) ? 0u : (uint32_t)(2 * OPW * 4);
        if (more) {
            cpa_tile<128>(smBase + nxt, A, ldA, m0, (kc + 1) * 64, t);
            cpa_tile<128>(smBase + nxt + OPW * 4, B, ldB, n0, (kc + 1) * 64, t);
            CPA_COMMIT();
        }
        if (more) CPA_WAIT1(); else CPA_WAIT0();
        __syncthreads();

        const uint32_t aBuf = smBase + cur;
        const uint32_t bBuf = aBuf + (uint32_t)(OPW * 4);

        uint32_t af[2][4][4], bf[2][8][2];
        load_frags128(aBuf, bBuf, laneA, laneB, 0, af[0], bf[0]);
        #pragma unroll
        for (int ks = 0; ks < 4; ks++) {
            const int cb = ks & 1;
            if (ks < 3)
                load_frags128(aBuf, bBuf, laneA, laneB, ks + 1, af[cb ^ 1], bf[cb ^ 1]);
            #pragma unroll
            for (int mf = 0; mf < 4; mf++)
                #pragma unroll
                for (int nf = 0; nf < 8; nf++)
                    mma16816(acc[mf][nf], af[cb][mf], bf[cb][nf]);
        }
        __syncthreads();
    }

    #pragma unroll
    for (int mf = 0; mf < 4; mf++) {
        const int r0 = m0 + wm * 64 + mf * 16 + grp;
        #pragma unroll
        for (int nf = 0; nf < 8; nf++) {
            const int cc = n0 + wn * 64 + nf * 8 + 2 * tig;
            *reinterpret_cast<__half2*>(&C[(size_t)r0 * N + cc]) =
                __floats2half2_rn(acc[mf][nf][0] * scale, acc[mf][nf][1] * scale);
            *reinterpret_cast<__half2*>(&C[(size_t)(r0 + 8) * N + cc]) =
                __floats2half2_rn(acc[mf][nf][2] * scale, acc[mf][nf][3] * scale);
        }
    }
}

// ---------------------------------------------------------------------------
// Merged prep: blocks [0,512): GroupNorm; [512,1792): weight cvt; [1792,1798):
// bias concat. 256 threads each.
// ---------------------------------------------------------------------------
__global__ void __launch_bounds__(256) prep_kernel(
    const float* __restrict__ x, const float* __restrict__ gamma,
    const float* __restrict__ beta, __half* __restrict__ hnT,
    const float* __restrict__ w0, const float* __restrict__ w1,
    const float* __restrict__ w2, const float* __restrict__ w3,
    const float* __restrict__ b0, const float* __restrict__ b1,
    const float* __restrict__ b2,
    __half* __restrict__ wcat, __half* __restrict__ wp,
    float* __restrict__ bcat)
{
    const int bid = blockIdx.x;
    const int tid = threadIdx.x;

    if (bid >= 1792) {                       // bias concat
        const int i = (bid - 1792) * 256 + tid;
        if (i < 3 * CCH)
            bcat[i] = (i < 512) ? b0[i] : (i < 1024) ? b1[i - 512] : b2[i - 1024];
        return;
    }
    if (bid >= 512) {                        // weight convert
        const int zz = (bid - 512) >> 8;
        const int i = ((bid - 512) & 255) * 256 + tid;
        const float* src = (zz == 0) ? w0 : (zz == 1) ? w1 : (zz == 2) ? w2 : w3;
        __half* dst = (zz == 3) ? wp : (wcat + (size_t)zz * CCH * CCH);
        const float4 v = reinterpret_cast<const float4*>(src)[i];
        __half2* d = reinterpret_cast<__half2*>(dst) + i * 2;
        d[0] = __floats2half2_rn(v.x, v.y);
        d[1] = __floats2half2_rn(v.z, v.w);
        return;
    }

    // ---- GroupNorm ----
    const int g = bid & 15, b = bid >> 4;
    const int c0 = g * CPG;
    const size_t xbase = ((size_t)b * CCH + c0) * NTOK;

    __shared__ float rs[256], rss[256];
    __shared__ float gsc[CPG], gof[CPG];
    __shared__ __half smh[256 * 34];         // [token][channel], pitch 34 halves

    const float4* xp = reinterpret_cast<const float4*>(x + xbase);
    float s = 0.f, ss = 0.f;
    for (int i = tid; i < GSIZE / 4; i += 256) {
        const float4 v = xp[i];
        s  += v.x + v.y + v.z + v.w;
        ss += v.x * v.x + v.y * v.y + v.z * v.z + v.w * v.w;
    }
    rs[tid] = s; rss[tid] = ss;
    __syncthreads();
    for (int w = 128; w > 0; w >>= 1) {
        if (tid < w) { rs[tid] += rs[tid + w]; rss[tid] += rss[tid + w]; }
        __syncthreads();
    }
    const float mean = rs[0] * (1.f / GSIZE);
    const float var  = rss[0] * (1.f / GSIZE) - mean * mean;
    const float rstd = rsqrtf(var + 1e-6f);

    if (tid < CPG) {
        const float ga = gamma[c0 + tid] * rstd;
        gsc[tid] = ga;
        gof[tid] = beta[c0 + tid] - mean * ga;
    }
    __syncthreads();

    for (int tt = 0; tt < 4; tt++) {
        const int tok0 = tt * 256;
        // write: thread = token, loop channels; STS.16 conflict-free (17t mod 32)
        #pragma unroll 4
        for (int j = 0; j < 32; j++) {
            const float val = x[xbase + (size_t)j * NTOK + tok0 + tid];
            smh[tid * 34 + j] = __float2half(val * gsc[j] + gof[j]);
        }
        __syncthreads();
        // read: thread = token, 16 LDS.32 (pre-packed half2 pairs), 4x STG.128
        const size_t obase = ((size_t)b * NTOK + tok0 + tid) * CCH + c0;
        uint32_t wb[16];
        const uint32_t* row = reinterpret_cast<const uint32_t*>(&smh[tid * 34]);
        #pragma unroll
        for (int w = 0; w < 16; w++) wb[w] = row[w];
        #pragma unroll
        for (int qd = 0; qd < 4; qd++) {
            *reinterpret_cast<uint4*>(&hnT[obase + qd * 8]) =
                *reinterpret_cast<const uint4*>(&wb[qd * 4]);
        }
        __syncthreads();
    }
}

// ---------------------------------------------------------------------------
// Warp-per-row softmax, fp16 in/out, IN PLACE. Pure shuffle reductions.
// (per-row max == reference's global shift, by softmax shift invariance)
// ---------------------------------------------------------------------------
__global__ void __launch_bounds__(256) softmax_kernel(__half* __restrict__ at)
{
    const int wid = threadIdx.x >> 5, lane = threadIdx.x & 31;
    const size_t row = (size_t)blockIdx.y * NTOK + blockIdx.x * 8 + wid;
    uint4* p = reinterpret_cast<uint4*>(at + row * NTOK);

    uint4 raw[4];
    float v[4][8];
    float m = -3.4e38f;
    #pragma unroll
    for (int i = 0; i < 4; i++) {
        raw[i] = p[lane + 32 * i];
        const uint32_t* w = reinterpret_cast<const uint32_t*>(&raw[i]);
        #pragma unroll
        for (int j = 0; j < 4; j++) {
            const float2 f = __half22float2(*reinterpret_cast<const __half2*>(&w[j]));
            v[i][2 * j] = f.x; v[i][2 * j + 1] = f.y;
            m = fmaxf(m, fmaxf(f.x, f.y));
        }
    }
    #pragma unroll
    for (int off = 16; off > 0; off >>= 1)
        m = fmaxf(m, __shfl_xor_sync(0xFFFFFFFFu, m, off));

    float sum = 0.f;
    #pragma unroll
    for (int i = 0; i < 4; i++)
        #pragma unroll
        for (int j = 0; j < 8; j++) {
            v[i][j] = __expf(v[i][j] - m);
            sum += v[i][j];
        }
    #pragma unroll
    for (int off = 16; off > 0; off >>= 1)
        sum += __shfl_xor_sync(0xFFFFFFFFu, sum, off);
    const float inv = 1.f / sum;

    #pragma unroll
    for (int i = 0; i < 4; i++) {
        uint4 outw;
        uint32_t* w = reinterpret_cast<uint32_t*>(&outw);
        #pragma unroll
        for (int j = 0; j < 4; j++) {
            const __half2 h = __floats2half2_rn(v[i][2 * j] * inv, v[i][2 * j + 1] * inv);
            w[j] = *reinterpret_cast<const uint32_t*>(&h);
        }
        p[lane + 32 * i] = outw;
    }
}

// ---------------------------------------------------------------------------
extern "C" void kernel_launch(void* const* d_in, const int* in_sizes, int n_in,
                              void* d_out, int out_size)
{
    (void)in_sizes; (void)n_in; (void)out_size;
    const float* x     = (const float*)d_in[0];
    const float* gamma = (const float*)d_in[1];
    const float* beta  = (const float*)d_in[2];
    const float* wq    = (const float*)d_in[3];
    const float* bq    = (const float*)d_in[4];
    const float* wk    = (const float*)d_in[5];
    const float* bk    = (const float*)d_in[6];
    const float* wv    = (const float*)d_in[7];
    const float* bv    = (const float*)d_in[8];
    const float* wp    = (const float*)d_in[9];
    const float* bp    = (const float*)d_in[10];
    float* out = (float*)d_out;

    void *p0, *p1, *p3, *p4, *p5, *p6, *p7;
    cudaGetSymbolAddress(&p0, sc_hnT);
    cudaGetSymbolAddress(&p1, sc_qkv);
    cudaGetSymbolAddress(&p3, sc_at);
    cudaGetSymbolAddress(&p4, sc_oT);
    cudaGetSymbolAddress(&p5, sc_wcat);
    cudaGetSymbolAddress(&p6, sc_wp);
    cudaGetSymbolAddress(&p7, sc_bcat);
    __half* hnT  = (__half*)p0;
    __half* qkv  = (__half*)p1;
    __half* at   = (__half*)p3;
    __half* oT   = (__half*)p4;
    __half* wcat = (__half*)p5;
    __half* whp  = (__half*)p6;
    float*  bcat = (float*)p7;

    const size_t sHN  = (size_t)NTOK * CCH;
    const size_t sQKV = (size_t)NTOK * 3 * CCH;
    const size_t sS   = (size_t)NTOK * NTOK;

    cudaFuncSetAttribute(hgemm<0, 2, false, true>,
        cudaFuncAttributeMaxDynamicSharedMemorySize, GEMM_SMEM_BYTES);
    cudaFuncSetAttribute(hgemm_s,
        cudaFuncAttributeMaxDynamicSharedMemorySize, GEMM_SMEM_BYTES);
    cudaFuncSetAttribute(hgemm<1, 0, false, true>,
        cudaFuncAttributeMaxDynamicSharedMemorySize, GEMM_SMEM_BYTES);
    cudaFuncSetAttribute(hgemm<0, 1, true, false>,
        cudaFuncAttributeMaxDynamicSharedMemorySize, GEMM_SMEM_BYTES);

    // 0) prep: GN + weight/bias conversion, one launch
    prep_kernel<<<1798, 256>>>(x, gamma, beta, hnT,
                               wq, wk, wv, wp, bq, bk, bv,
                               wcat, whp, bcat);

    // 1) fused QKV: qkv[token][oc'] = hnT[token][c] . wcat[oc'][c] + bcat[oc']
    hgemm<0, 2, false, true><<<dim3(12, 8, BATCH), 256, GEMM_SMEM_BYTES>>>(
        hnT, wcat, bcat, nullptr, qkv, 3 * CCH, CCH, CCH, CCH,
        sHN, 0, sQKV, 0, 1.f);

    // 2) scores (fp16 out, 128-thr 64x64 variant)
    hgemm_s<<<dim3(8, 8, BATCH), 128, GEMM_SMEM_BYTES>>>(
        qkv, qkv + CCH, at, NTOK, CCH, 3 * CCH, 3 * CCH,
        sQKV, sQKV, sS, 0.04419417382415922f);

    // 3) softmax, in place on fp16 scores
    softmax_kernel<<<dim3(NTOK / 8, BATCH), 256>>>(at);

    // 4) oT[n][c] = sum_m at[n][m] * v[m][c]  (B native [k][n], ldmatrix.trans)
    hgemm<1, 0, false, true><<<dim3(4, 8, BATCH), 256, GEMM_SMEM_BYTES>>>(
        at, qkv + 2 * CCH, nullptr, nullptr, oT, CCH, NTOK, NTOK, 3 * CCH,
        sS, sQKV, sHN, 0, 1.f);

    // 5) out[oc][n] = x + wp[oc][:] . oT[n][:] + bp[oc]
    hgemm<0, 1, true, false><<<dim3(8, 4, BATCH), 256, GEMM_SMEM_BYTES>>>(
        whp, oT, bp, x, out, NTOK, CCH, CCH, CCH,
        0, sHN, sHN, sHN, 1.f);
}

// round 17
// speedup vs baseline: 1.0139x; 1.0006x over previous
#include <cuda_runtime.h>
#include <cuda_fp16.h>
#include <cstdint>
#include <cstddef>

// ===========================================================================
// AttnBlock, fp16 mma.sync, token-major intermediates, cp.async pipeline.
// R17 experiment: scores GEMM uses fp16 accumulators (2x-rate hypothesis).
// b=32, c=512, n=1024, groups=16
// ===========================================================================

#define BATCH 32
#define CCH   512
#define NTOK  1024
#define NGRP  16
#define CPG   (CCH / NGRP)
#define GSIZE (CPG * NTOK)

__device__ __half sc_hnT [(size_t)BATCH * NTOK * CCH];
__device__ __half sc_qkv [(size_t)BATCH * NTOK * 3 * CCH];
__device__ __half sc_at  [(size_t)BATCH * NTOK * NTOK];   // scores -> attn (in place)
__device__ __half sc_oT  [(size_t)BATCH * NTOK * CCH];
__device__ __half sc_wcat[(size_t)3 * CCH * CCH];
__device__ __half sc_wp  [(size_t)CCH * CCH];
__device__ float  sc_bcat[3 * CCH];

#define PITCHW  36
#define PITCHBT 68
#define OPW     (128 * PITCHW)             // words per operand slot (4608)
#define GEMM_SMEM_BYTES (4 * OPW * 4)      // A0 B0 A1 B1 = 73728 B

__device__ __forceinline__ void cpa16(uint32_t saddr, const void* g) {
    asm volatile("cp.async.cg.shared.global [%0], [%1], 16;"
                 :: "r"(saddr), "l"(g));
}
#define CPA_COMMIT() asm volatile("cp.async.commit_group;" ::: "memory")
#define CPA_WAIT1()  asm volatile("cp.async.wait_group 1;" ::: "memory")
#define CPA_WAIT0()  asm volatile("cp.async.wait_group 0;" ::: "memory")

// row-major tile: 128 rows x 64 halves; NT = thread count
template<int NT>
__device__ __forceinline__ void cpa_tile(uint32_t sbase_bytes,
                                         const __half* __restrict__ src,
                                         int ld, int row0, int k0, int t) {
    #pragma unroll
    for (int j = 0; j < 1024 / NT; j++) {
        const int idx = t + NT * j;
        const int r = idx >> 3, c8 = idx & 7;
        const void* g = src + (size_t)(row0 + r) * ld + k0 + c8 * 8;
        cpa16(sbase_bytes + (uint32_t)(r * PITCHW + c8 * 4) * 4u, g);
    }
}

// trans tile: 64 k-rows x 128 n-halves, native [k][n] layout
template<int NT>
__device__ __forceinline__ void cpa_tile_bt(uint32_t sbase_bytes,
                                            const __half* __restrict__ src,
                                            int ld, int n0, int k0, int t) {
    #pragma unroll
    for (int j = 0; j < 1024 / NT; j++) {
        const int idx = t + NT * j;
        const int r = idx >> 4, c16 = idx & 15;
        const void* g = src + (size_t)(k0 + r) * ld + n0 + c16 * 8;
        cpa16(sbase_bytes + (uint32_t)(r * PITCHBT + c16 * 4) * 4u, g);
    }
}

__device__ __forceinline__ void mma16816(float d[4], const uint32_t a[4],
                                         const uint32_t b[2]) {
    asm volatile(
        "mma.sync.aligned.m16n8k16.row.col.f32.f16.f16.f32 "
        "{%0,%1,%2,%3}, {%4,%5,%6,%7}, {%8,%9}, {%0,%1,%2,%3};"
        : "+f"(d[0]), "+f"(d[1]), "+f"(d[2]), "+f"(d[3])
        : "r"(a[0]), "r"(a[1]), "r"(a[2]), "r"(a[3]), "r"(b[0]), "r"(b[1]));
}
// fp16 accumulator variant (experiment: 2x-rate hypothesis)
__device__ __forceinline__ void mma16816h(uint32_t d[2], const uint32_t a[4],
                                          const uint32_t b[2]) {
    asm volatile(
        "mma.sync.aligned.m16n8k16.row.col.f16.f16.f16.f16 "
        "{%0,%1}, {%2,%3,%4,%5}, {%6,%7}, {%0,%1};"
        : "+r"(d[0]), "+r"(d[1])
        : "r"(a[0]), "r"(a[1]), "r"(a[2]), "r"(a[3]), "r"(b[0]), "r"(b[1]));
}
#define LDMX4(r0, r1, r2, r3, addr) \
    asm volatile("ldmatrix.sync.aligned.m8n8.x4.shared.b16 {%0,%1,%2,%3}, [%4];" \
                 : "=r"(r0), "=r"(r1), "=r"(r2), "=r"(r3) : "r"(addr))
#define LDMX4T(r0, r1, r2, r3, addr) \
    asm volatile("ldmatrix.sync.aligned.m8n8.x4.trans.shared.b16 {%0,%1,%2,%3}, [%4];" \
                 : "=r"(r0), "=r"(r1), "=r"(r2), "=r"(r3) : "r"(addr))

// ---------------------------------------------------------------------------
// 256-thread GEMM (8 warps, 2Mx4N, warp tile 64x32), f32 accumulate.
// ---------------------------------------------------------------------------
template<int BT>
__device__ __forceinline__ void load_frags256(uint32_t aBuf, uint32_t bBuf,
                                              uint32_t laneA, uint32_t laneB,
                                              int ks, uint32_t af[4][4],
                                              uint32_t bf[4][2]) {
    #pragma unroll
    for (int mf = 0; mf < 4; mf++)
        LDMX4(af[mf][0], af[mf][1], af[mf][2], af[mf][3],
              aBuf + laneA + (uint32_t)(mf * 16 * PITCHW * 4 + ks * 32));
    if (BT == 0) {
        LDMX4(bf[0][0], bf[0][1], bf[1][0], bf[1][1],
              bBuf + laneB + (uint32_t)(ks * 32));
        LDMX4(bf[2][0], bf[2][1], bf[3][0], bf[3][1],
              bBuf + laneB + (uint32_t)(16 * PITCHW * 4 + ks * 32));
    } else {
        LDMX4T(bf[0][0], bf[0][1], bf[1][0], bf[1][1],
               bBuf + laneB + (uint32_t)(ks * 16 * PITCHBT * 4));
        LDMX4T(bf[2][0], bf[2][1], bf[3][0], bf[3][1],
               bBuf + laneB + (uint32_t)(ks * 16 * PITCHBT * 4 + 32));
    }
}

template<int BT, int BIASMODE, bool RESID, bool HOUT>
__global__ void __launch_bounds__(256, 2) hgemm(
    const __half* __restrict__ A, const __half* __restrict__ B,
    const float* __restrict__ bias, const float* __restrict__ resid,
    void* __restrict__ Cv, int N, int K, int ldA, int ldB,
    size_t sA, size_t sB, size_t sC, size_t sR, float scale)
{
    extern __shared__ __align__(16) uint32_t smbuf[];

    const int z = blockIdx.z;
    A += (size_t)z * sA;
    B += (size_t)z * sB;
    const float* R = RESID ? (resid + (size_t)z * sR) : nullptr;

    const int n0 = blockIdx.x * 128, m0 = blockIdx.y * 128;
    const int t = threadIdx.x;
    const int wid = t >> 5, lane = t & 31;
    const int wm = wid & 1, wn = wid >> 1;
    const int grp = lane >> 2, tig = lane & 3;

    const uint32_t smBase = (uint32_t)__cvta_generic_to_shared(smbuf);

    float acc[4][4][4] = {};

    cpa_tile<256>(smBase, A, ldA, m0, 0, t);
    if (BT == 0) cpa_tile<256>(smBase + OPW * 4, B, ldB, n0, 0, t);
    else         cpa_tile_bt<256>(smBase + OPW * 4, B, ldB, n0, 0, t);
    CPA_COMMIT();

    const uint32_t laneA =
        ((uint32_t)(wm * 64 + (lane & 7) + 8 * ((lane >> 3) & 1)) * PITCHW
         + 4u * ((lane >> 4) & 1)) * 4u;
    const uint32_t laneB = (BT == 0)
        ? ((uint32_t)(wn * 32 + (lane & 7) + 8 * ((lane >> 4) & 1)) * PITCHW
           + 4u * ((lane >> 3) & 1)) * 4u
        : (uint32_t)((lane & 7) + 8 * ((lane >> 3) & 1)) * (PITCHBT * 4)
          + (uint32_t)(wn * 32 + 8 * ((lane >> 4) & 1)) * 2u;

    const int NK = K >> 6;
    for (int kc = 0; kc < NK; kc++) {
        const bool more = (kc + 1 < NK);
        const uint32_t cur = (kc & 1) ? (uint32_t)(2 * OPW * 4) : 0u;
        const uint32_t nxt = (kc & 1) ? 0u : (uint32_t)(2 * OPW * 4);
        if (more) {
            cpa_tile<256>(smBase + nxt, A, ldA, m0, (kc + 1) * 64, t);
            if (BT == 0) cpa_tile<256>(smBase + nxt + OPW * 4, B, ldB, n0, (kc + 1) * 64, t);
            else         cpa_tile_bt<256>(smBase + nxt + OPW * 4, B, ldB, n0, (kc + 1) * 64, t);
            CPA_COMMIT();
        }
        if (more) CPA_WAIT1(); else CPA_WAIT0();
        __syncthreads();

        const uint32_t aBuf = smBase + cur;
        const uint32_t bBuf = aBuf + (uint32_t)(OPW * 4);

        uint32_t af[2][4][4], bf[2][4][2];
        load_frags256<BT>(aBuf, bBuf, laneA, laneB, 0, af[0], bf[0]);
        #pragma unroll
        for (int ks = 0; ks < 4; ks++) {
            const int cb = ks & 1;
            if (ks < 3)
                load_frags256<BT>(aBuf, bBuf, laneA, laneB, ks + 1, af[cb ^ 1], bf[cb ^ 1]);
            #pragma unroll
            for (int mf = 0; mf < 4; mf++)
                #pragma unroll
                for (int nf = 0; nf < 4; nf++)
                    mma16816(acc[mf][nf], af[cb][mf], bf[cb][nf]);
        }
        __syncthreads();
    }

    #pragma unroll
    for (int mf = 0; mf < 4; mf++) {
        const int r0 = m0 + wm * 64 + mf * 16 + grp;
        const float ba0 = (BIASMODE == 1) ? bias[r0] : 0.f;
        const float ba1 = (BIASMODE == 1) ? bias[r0 + 8] : 0.f;
        #pragma unroll
        for (int nf = 0; nf < 4; nf++) {
            const int cc = n0 + wn * 32 + nf * 8 + 2 * tig;
            float cb0 = 0.f, cb1 = 0.f;
            if (BIASMODE == 2) {
                const float2 cb = *reinterpret_cast<const float2*>(&bias[cc]);
                cb0 = cb.x; cb1 = cb.y;
            }
            float2 v0, v1;
            v0.x = acc[mf][nf][0] * scale + ba0 + cb0;
            v0.y = acc[mf][nf][1] * scale + ba0 + cb1;
            v1.x = acc[mf][nf][2] * scale + ba1 + cb0;
            v1.y = acc[mf][nf][3] * scale + ba1 + cb1;
            if (RESID) {
                const float2 q0 = *reinterpret_cast<const float2*>(&R[(size_t)r0 * N + cc]);
                const float2 q1 = *reinterpret_cast<const float2*>(&R[(size_t)(r0 + 8) * N + cc]);
                v0.x += q0.x; v0.y += q0.y;
                v1.x += q1.x; v1.y += q1.y;
            }
            if (HOUT) {
                __half* C = (__half*)Cv + (size_t)z * sC;
                *reinterpret_cast<__half2*>(&C[(size_t)r0 * N + cc]) =
                    __floats2half2_rn(v0.x, v0.y);
                *reinterpret_cast<__half2*>(&C[(size_t)(r0 + 8) * N + cc]) =
                    __floats2half2_rn(v1.x, v1.y);
            } else {
                float* C = (float*)Cv + (size_t)z * sC;
                *reinterpret_cast<float2*>(&C[(size_t)r0 * N + cc]) = v0;
                *reinterpret_cast<float2*>(&C[(size_t)(r0 + 8) * N + cc]) = v1;
            }
        }
    }
}

// ---------------------------------------------------------------------------
// Scores GEMM: 128 threads, warp tile 64x64, fp16 ACCUMULATORS (experiment).
// ---------------------------------------------------------------------------
__device__ __forceinline__ void load_frags128(uint32_t aBuf, uint32_t bBuf,
                                              uint32_t laneA, uint32_t laneB,
                                              int ks, uint32_t af[4][4],
                                              uint32_t bf[8][2]) {
    #pragma unroll
    for (int mf = 0; mf < 4; mf++)
        LDMX4(af[mf][0], af[mf][1], af[mf][2], af[mf][3],
              aBuf + laneA + (uint32_t)(mf * 16 * PITCHW * 4 + ks * 32));
    #pragma unroll
    for (int p = 0; p < 4; p++)
        LDMX4(bf[2 * p][0], bf[2 * p][1], bf[2 * p + 1][0], bf[2 * p + 1][1],
              bBuf + laneB + (uint32_t)(p * 16 * PITCHW * 4 + ks * 32));
}

__global__ void __launch_bounds__(128, 2) hgemm_s(
    const __half* __restrict__ A, const __half* __restrict__ B,
    __half* __restrict__ C, int N, int K, int ldA, int ldB,
    size_t sA, size_t sB, size_t sC, float scale)
{
    extern __shared__ __align__(16) uint32_t smbuf[];

    const int z = blockIdx.z;
    A += (size_t)z * sA;
    B += (size_t)z * sB;
    C += (size_t)z * sC;

    const int n0 = blockIdx.x * 128, m0 = blockIdx.y * 128;
    const int t = threadIdx.x;
    const int wid = t >> 5, lane = t & 31;
    const int wm = wid & 1, wn = wid >> 1;
    const int grp = lane >> 2, tig = lane & 3;

    const uint32_t smBase = (uint32_t)__cvta_generic_to_shared(smbuf);

    uint32_t acc[4][8][2] = {};   // fp16x2 accumulators

    cpa_tile<128>(smBase, A, ldA, m0, 0, t);
    cpa_tile<128>(smBase + OPW * 4, B, ldB, n0, 0, t);
    CPA_COMMIT();

    const uint32_t laneA =
        ((uint32_t)(wm * 64 + (lane & 7) + 8 * ((lane >> 3) & 1)) * PITCHW
         + 4u * ((lane >> 4) & 1)) * 4u;
    const uint32_t laneB =
        ((uint32_t)(wn * 64 + (lane & 7) + 8 * ((lane >> 4) & 1)) * PITCHW
         + 4u * ((lane >> 3) & 1)) * 4u;

    const int NK = K >> 6;
    for (int kc = 0; kc < NK; kc++) {
        const bool more = (kc + 1 < NK);
        const uint32_t cur = (kc & 1) ? (uint32_t)(2 * OPW * 4) : 0u;
        const uint32_t nxt = (kc & 1) ? 0u : (uint32_t)(2 * OPW * 4);
        if (more) {
            cpa_tile<128>(smBase + nxt, A, ldA, m0, (kc + 1) * 64, t);
            cpa_tile<128>(smBase + nxt + OPW * 4, B, ldB, n0, (kc + 1) * 64, t);
            CPA_COMMIT();
        }
        if (more) CPA_WAIT1(); else CPA_WAIT0();
        __syncthreads();

        const uint32_t aBuf = smBase + cur;
        const uint32_t bBuf = aBuf + (uint32_t)(OPW * 4);

        uint32_t af[2][4][4], bf[2][8][2];
        load_frags128(aBuf, bBuf, laneA, laneB, 0, af[0], bf[0]);
        #pragma unroll
        for (int ks = 0; ks < 4; ks++) {
            const int cb = ks & 1;
            if (ks < 3)
                load_frags128(aBuf, bBuf, laneA, laneB, ks + 1, af[cb ^ 1], bf[cb ^ 1]);
            #pragma unroll
            for (int mf = 0; mf < 4; mf++)
                #pragma unroll
                for (int nf = 0; nf < 8; nf++)
                    mma16816h(acc[mf][nf], af[cb][mf], bf[cb][nf]);
        }
        __syncthreads();
    }

    // epilogue: unpack fp16 acc -> scale -> store fp16
    #pragma unroll
    for (int mf = 0; mf < 4; mf++) {
        const int r0 = m0 + wm * 64 + mf * 16 + grp;
        #pragma unroll
        for (int nf = 0; nf < 8; nf++) {
            const int cc = n0 + wn * 64 + nf * 8 + 2 * tig;
            const float2 f0 = __half22float2(
                *reinterpret_cast<const __half2*>(&acc[mf][nf][0]));
            const float2 f1 = __half22float2(
                *reinterpret_cast<const __half2*>(&acc[mf][nf][1]));
            *reinterpret_cast<__half2*>(&C[(size_t)r0 * N + cc]) =
                __floats2half2_rn(f0.x * scale, f0.y * scale);
            *reinterpret_cast<__half2*>(&C[(size_t)(r0 + 8) * N + cc]) =
                __floats2half2_rn(f1.x * scale, f1.y * scale);
        }
    }
}

// ---------------------------------------------------------------------------
// Merged prep: blocks [0,512): GroupNorm; [512,1792): weight cvt; [1792,1798):
// bias concat. 256 threads each.
// ---------------------------------------------------------------------------
__global__ void __launch_bounds__(256) prep_kernel(
    const float* __restrict__ x, const float* __restrict__ gamma,
    const float* __restrict__ beta, __half* __restrict__ hnT,
    const float* __restrict__ w0, const float* __restrict__ w1,
    const float* __restrict__ w2, const float* __restrict__ w3,
    const float* __restrict__ b0, const float* __restrict__ b1,
    const float* __restrict__ b2,
    __half* __restrict__ wcat, __half* __restrict__ wp,
    float* __restrict__ bcat)
{
    const int bid = blockIdx.x;
    const int tid = threadIdx.x;

    if (bid >= 1792) {
        const int i = (bid - 1792) * 256 + tid;
        if (i < 3 * CCH)
            bcat[i] = (i < 512) ? b0[i] : (i < 1024) ? b1[i - 512] : b2[i - 1024];
        return;
    }
    if (bid >= 512) {
        const int zz = (bid - 512) >> 8;
        const int i = ((bid - 512) & 255) * 256 + tid;
        const float* src = (zz == 0) ? w0 : (zz == 1) ? w1 : (zz == 2) ? w2 : w3;
        __half* dst = (zz == 3) ? wp : (wcat + (size_t)zz * CCH * CCH);
        const float4 v = reinterpret_cast<const float4*>(src)[i];
        __half2* d = reinterpret_cast<__half2*>(dst) + i * 2;
        d[0] = __floats2half2_rn(v.x, v.y);
        d[1] = __floats2half2_rn(v.z, v.w);
        return;
    }

    const int g = bid & 15, b = bid >> 4;
    const int c0 = g * CPG;
    const size_t xbase = ((size_t)b * CCH + c0) * NTOK;

    __shared__ float rs[256], rss[256];
    __shared__ float gsc[CPG], gof[CPG];
    __shared__ __half smh[256 * 34];

    const float4* xp = reinterpret_cast<const float4*>(x + xbase);
    float s = 0.f, ss = 0.f;
    for (int i = tid; i < GSIZE / 4; i += 256) {
        const float4 v = xp[i];
        s  += v.x + v.y + v.z + v.w;
        ss += v.x * v.x + v.y * v.y + v.z * v.z + v.w * v.w;
    }
    rs[tid] = s; rss[tid] = ss;
    __syncthreads();
    for (int w = 128; w > 0; w >>= 1) {
        if (tid < w) { rs[tid] += rs[tid + w]; rss[tid] += rss[tid + w]; }
        __syncthreads();
    }
    const float mean = rs[0] * (1.f / GSIZE);
    const float var  = rss[0] * (1.f / GSIZE) - mean * mean;
    const float rstd = rsqrtf(var + 1e-6f);

    if (tid < CPG) {
        const float ga = gamma[c0 + tid] * rstd;
        gsc[tid] = ga;
        gof[tid] = beta[c0 + tid] - mean * ga;
    }
    __syncthreads();

    for (int tt = 0; tt < 4; tt++) {
        const int tok0 = tt * 256;
        #pragma unroll 4
        for (int j = 0; j < 32; j++) {
            const float val = x[xbase + (size_t)j * NTOK + tok0 + tid];
            smh[tid * 34 + j] = __float2half(val * gsc[j] + gof[j]);
        }
        __syncthreads();
        const size_t obase = ((size_t)b * NTOK + tok0 + tid) * CCH + c0;
        uint32_t wb[16];
        const uint32_t* row = reinterpret_cast<const uint32_t*>(&smh[tid * 34]);
        #pragma unroll
        for (int w = 0; w < 16; w++) wb[w] = row[w];
        #pragma unroll
        for (int qd = 0; qd < 4; qd++) {
            *reinterpret_cast<uint4*>(&hnT[obase + qd * 8]) =
                *reinterpret_cast<const uint4*>(&wb[qd * 4]);
        }
        __syncthreads();
    }
}

// ---------------------------------------------------------------------------
// Warp-per-row softmax, fp16 in/out, IN PLACE. Pure shuffle reductions.
// ---------------------------------------------------------------------------
__global__ void __launch_bounds__(256) softmax_kernel(__half* __restrict__ at)
{
    const int wid = threadIdx.x >> 5, lane = threadIdx.x & 31;
    const size_t row = (size_t)blockIdx.y * NTOK + blockIdx.x * 8 + wid;
    uint4* p = reinterpret_cast<uint4*>(at + row * NTOK);

    uint4 raw[4];
    float v[4][8];
    float m = -3.4e38f;
    #pragma unroll
    for (int i = 0; i < 4; i++) {
        raw[i] = p[lane + 32 * i];
        const uint32_t* w = reinterpret_cast<const uint32_t*>(&raw[i]);
        #pragma unroll
        for (int j = 0; j < 4; j++) {
            const float2 f = __half22float2(*reinterpret_cast<const __half2*>(&w[j]));
            v[i][2 * j] = f.x; v[i][2 * j + 1] = f.y;
            m = fmaxf(m, fmaxf(f.x, f.y));
        }
    }
    #pragma unroll
    for (int off = 16; off > 0; off >>= 1)
        m = fmaxf(m, __shfl_xor_sync(0xFFFFFFFFu, m, off));

    float sum = 0.f;
    #pragma unroll
    for (int i = 0; i < 4; i++)
        #pragma unroll
        for (int j = 0; j < 8; j++) {
            v[i][j] = __expf(v[i][j] - m);
            sum += v[i][j];
        }
    #pragma unroll
    for (int off = 16; off > 0; off >>= 1)
        sum += __shfl_xor_sync(0xFFFFFFFFu, sum, off);
    const float inv = 1.f / sum;

    #pragma unroll
    for (int i = 0; i < 4; i++) {
        uint4 outw;
        uint32_t* w = reinterpret_cast<uint32_t*>(&outw);
        #pragma unroll
        for (int j = 0; j < 4; j++) {
            const __half2 h = __floats2half2_rn(v[i][2 * j] * inv, v[i][2 * j + 1] * inv);
            w[j] = *reinterpret_cast<const uint32_t*>(&h);
        }
        p[lane + 32 * i] = outw;
    }
}

// ---------------------------------------------------------------------------
extern "C" void kernel_launch(void* const* d_in, const int* in_sizes, int n_in,
                              void* d_out, int out_size)
{
    (void)in_sizes; (void)n_in; (void)out_size;
    const float* x     = (const float*)d_in[0];
    const float* gamma = (const float*)d_in[1];
    const float* beta  = (const float*)d_in[2];
    const float* wq    = (const float*)d_in[3];
    const float* bq    = (const float*)d_in[4];
    const float* wk    = (const float*)d_in[5];
    const float* bk    = (const float*)d_in[6];
    const float* wv    = (const float*)d_in[7];
    const float* bv    = (const float*)d_in[8];
    const float* wp    = (const float*)d_in[9];
    const float* bp    = (const float*)d_in[10];
    float* out = (float*)d_out;

    void *p0, *p1, *p3, *p4, *p5, *p6, *p7;
    cudaGetSymbolAddress(&p0, sc_hnT);
    cudaGetSymbolAddress(&p1, sc_qkv);
    cudaGetSymbolAddress(&p3, sc_at);
    cudaGetSymbolAddress(&p4, sc_oT);
    cudaGetSymbolAddress(&p5, sc_wcat);
    cudaGetSymbolAddress(&p6, sc_wp);
    cudaGetSymbolAddress(&p7, sc_bcat);
    __half* hnT  = (__half*)p0;
    __half* qkv  = (__half*)p1;
    __half* at   = (__half*)p3;
    __half* oT   = (__half*)p4;
    __half* wcat = (__half*)p5;
    __half* whp  = (__half*)p6;
    float*  bcat = (float*)p7;

    const size_t sHN  = (size_t)NTOK * CCH;
    const size_t sQKV = (size_t)NTOK * 3 * CCH;
    const size_t sS   = (size_t)NTOK * NTOK;

    cudaFuncSetAttribute(hgemm<0, 2, false, true>,
        cudaFuncAttributeMaxDynamicSharedMemorySize, GEMM_SMEM_BYTES);
    cudaFuncSetAttribute(hgemm_s,
        cudaFuncAttributeMaxDynamicSharedMemorySize, GEMM_SMEM_BYTES);
    cudaFuncSetAttribute(hgemm<1, 0, false, true>,
        cudaFuncAttributeMaxDynamicSharedMemorySize, GEMM_SMEM_BYTES);
    cudaFuncSetAttribute(hgemm<0, 1, true, false>,
        cudaFuncAttributeMaxDynamicSharedMemorySize, GEMM_SMEM_BYTES);

    // 0) prep: GN + weight/bias conversion, one launch
    prep_kernel<<<1798, 256>>>(x, gamma, beta, hnT,
                               wq, wk, wv, wp, bq, bk, bv,
                               wcat, whp, bcat);

    // 1) fused QKV
    hgemm<0, 2, false, true><<<dim3(12, 8, BATCH), 256, GEMM_SMEM_BYTES>>>(
        hnT, wcat, bcat, nullptr, qkv, 3 * CCH, CCH, CCH, CCH,
        sHN, 0, sQKV, 0, 1.f);

    // 2) scores (fp16 accumulate experiment)
    hgemm_s<<<dim3(8, 8, BATCH), 128, GEMM_SMEM_BYTES>>>(
        qkv, qkv + CCH, at, NTOK, CCH, 3 * CCH, 3 * CCH,
        sQKV, sQKV, sS, 0.04419417382415922f);

    // 3) softmax, in place on fp16 scores
    softmax_kernel<<<dim3(NTOK / 8, BATCH), 256>>>(at);

    // 4) oT[n][c] = sum_m at[n][m] * v[m][c]  (B native [k][n], ldmatrix.trans)
    hgemm<1, 0, false, true><<<dim3(4, 8, BATCH), 256, GEMM_SMEM_BYTES>>>(
        at, qkv + 2 * CCH, nullptr, nullptr, oT, CCH, NTOK, NTOK, 3 * CCH,
        sS, sQKV, sHN, 0, 1.f);

    // 5) out = x + wp @ oT + bp
    hgemm<0, 1, true, false><<<dim3(8, 4, BATCH), 256, GEMM_SMEM_BYTES>>>(
        whp, oT, bp, x, out, NTOK, CCH, CCH, CCH,
        0, sHN, sHN, sHN, 1.f);
}